// round 1
// baseline (speedup 1.0000x reference)
#include <cuda_runtime.h>
#include <cstdint>
#include <cstddef>

// Problem constants
#define BB 32
#define SS 8
#define TT 512
#define CC 128
#define HSZ 128

// Scratch (device globals; no runtime allocation allowed)
__device__ float g_M[CC * CC];                       // Wq @ Wk^T, tf32-rounded
__device__ float g_y[BB * TT * CC];                  // x @ M, tf32-rounded
__device__ float g_v[BB * TT * HSZ];                 // x @ Wv, tf32-rounded
__device__ float g_score[(size_t)BB * TT * TT];      // fp32 scores (33.5 MB)

__device__ __forceinline__ unsigned f2tf(float x) {
    unsigned u;
    asm("cvt.rna.tf32.f32 %0, %1;" : "=r"(u) : "f"(x));
    return u;
}
__device__ __forceinline__ float f2tf_f(float x) { return __uint_as_float(f2tf(x)); }

__device__ __forceinline__ void mma_tf32(float& c0, float& c1, float& c2, float& c3,
                                         unsigned a0, unsigned a1, unsigned a2, unsigned a3,
                                         unsigned b0, unsigned b1) {
    asm volatile(
        "mma.sync.aligned.m16n8k8.row.col.f32.tf32.tf32.f32 "
        "{%0,%1,%2,%3},{%4,%5,%6,%7},{%8,%9},{%0,%1,%2,%3};\n"
        : "+f"(c0), "+f"(c1), "+f"(c2), "+f"(c3)
        : "r"(a0), "r"(a1), "r"(a2), "r"(a3), "r"(b0), "r"(b1));
}

// ---------------------------------------------------------------------------
// K1: M = Wq @ Wk^T  (fp32 FFMA, rounded to tf32 on store)
// grid(128), block(128), dyn smem = 128*132*4
// ---------------------------------------------------------------------------
__global__ void k_wqwk(const float* __restrict__ Wq, const float* __restrict__ Wk) {
    extern __shared__ float sm[];  // sWk[128][132]
    int tid = threadIdx.x;
    int c1 = blockIdx.x;
    for (int i = tid; i < CC * CC; i += 128) {
        sm[(i >> 7) * 132 + (i & 127)] = Wk[i];
    }
    __syncthreads();
    const float* wqr = Wq + c1 * CC;
    float acc = 0.f;
#pragma unroll 8
    for (int h = 0; h < CC; h++) acc += wqr[h] * sm[tid * 132 + h];
    g_M[c1 * CC + tid] = f2tf_f(acc);
}

// ---------------------------------------------------------------------------
// K2a: y = x @ M,  v = x @ Wv   (tf32 mma)
// grid(B*T/64), block(128), dyn smem = 64*132*4
// ---------------------------------------------------------------------------
__global__ void __launch_bounds__(128) k_yv(const float* __restrict__ x,
                                            const float* __restrict__ Wv) {
    extern __shared__ float sm[];  // sx[64][132] tf32-rounded
    int tid = threadIdx.x;
    int row0 = blockIdx.x * 64;
    for (int f = tid; f < 64 * CC / 4; f += 128) {
        int r = f >> 5, c = (f & 31) * 4;
        float4 v4 = *reinterpret_cast<const float4*>(&x[(size_t)(row0 + r) * CC + c]);
        float4 o;
        o.x = f2tf_f(v4.x); o.y = f2tf_f(v4.y); o.z = f2tf_f(v4.z); o.w = f2tf_f(v4.w);
        *reinterpret_cast<float4*>(&sm[r * 132 + c]) = o;
    }
    __syncthreads();
    int lane = tid & 31, w = tid >> 5;
    int gid = lane >> 2, tig = lane & 3;
    int mrow = w * 16;
    for (int nt = 0; nt < 32; nt++) {
        bool isv = nt >= 16;
        const float* Bsrc = isv ? Wv : g_M;
        int n = (nt & 15) * 8;
        float c0 = 0, c1 = 0, c2 = 0, c3 = 0;
#pragma unroll
        for (int kk = 0; kk < 16; kk++) {
            int k = kk * 8;
            unsigned a0 = __float_as_uint(sm[(mrow + gid) * 132 + k + tig]);
            unsigned a1 = __float_as_uint(sm[(mrow + gid + 8) * 132 + k + tig]);
            unsigned a2 = __float_as_uint(sm[(mrow + gid) * 132 + k + tig + 4]);
            unsigned a3 = __float_as_uint(sm[(mrow + gid + 8) * 132 + k + tig + 4]);
            float bv0 = Bsrc[(k + tig) * CC + n + gid];
            float bv1 = Bsrc[(k + tig + 4) * CC + n + gid];
            unsigned b0 = isv ? f2tf(bv0) : __float_as_uint(bv0);
            unsigned b1 = isv ? f2tf(bv1) : __float_as_uint(bv1);
            mma_tf32(c0, c1, c2, c3, a0, a1, a2, a3, b0, b1);
        }
        float* dst = isv ? g_v : g_y;
        int r0 = row0 + mrow + gid;
        dst[(size_t)r0 * CC + n + 2 * tig]           = f2tf_f(c0);
        dst[(size_t)r0 * CC + n + 2 * tig + 1]       = f2tf_f(c1);
        dst[(size_t)(r0 + 8) * CC + n + 2 * tig]     = f2tf_f(c2);
        dst[(size_t)(r0 + 8) * CC + n + 2 * tig + 1] = f2tf_f(c3);
    }
}

// ---------------------------------------------------------------------------
// K2b: score[b, t, u] = (y[b,t,:] . x[b,u,:]) * C^-0.5   (tf32 mma)
// grid(8, 32) = (t_tile, b), block(128), dyn smem = 2*64*132*4
// ---------------------------------------------------------------------------
__global__ void __launch_bounds__(128) k_score(const float* __restrict__ x) {
    extern __shared__ float sm[];
    float* sy = sm;              // [64][132]
    float* sxu = sm + 64 * 132;  // [64][132]
    int tid = threadIdx.x;
    int b = blockIdx.y;
    int t0 = blockIdx.x * 64;
    for (int f = tid; f < 64 * CC / 4; f += 128) {
        int r = f >> 5, c = (f & 31) * 4;
        *reinterpret_cast<float4*>(&sy[r * 132 + c]) =
            *reinterpret_cast<const float4*>(&g_y[(size_t)(b * TT + t0 + r) * CC + c]);
    }
    int lane = tid & 31, w = tid >> 5, gid = lane >> 2, tig = lane & 3;
    int mrow = w * 16;
    const float scl = 0.08838834764831843f;  // 128^-0.5
    for (int u0 = 0; u0 < TT; u0 += 64) {
        __syncthreads();
        for (int f = tid; f < 64 * CC / 4; f += 128) {
            int r = f >> 5, c = (f & 31) * 4;
            float4 v4 = *reinterpret_cast<const float4*>(&x[(size_t)(b * TT + u0 + r) * CC + c]);
            float4 o;
            o.x = f2tf_f(v4.x); o.y = f2tf_f(v4.y); o.z = f2tf_f(v4.z); o.w = f2tf_f(v4.w);
            *reinterpret_cast<float4*>(&sxu[r * 132 + c]) = o;
        }
        __syncthreads();
        for (int nt = 0; nt < 8; nt++) {
            int n = nt * 8;
            float c0 = 0, c1 = 0, c2 = 0, c3 = 0;
#pragma unroll
            for (int kk = 0; kk < 16; kk++) {
                int k = kk * 8;
                unsigned a0 = __float_as_uint(sy[(mrow + gid) * 132 + k + tig]);
                unsigned a1 = __float_as_uint(sy[(mrow + gid + 8) * 132 + k + tig]);
                unsigned a2 = __float_as_uint(sy[(mrow + gid) * 132 + k + tig + 4]);
                unsigned a3 = __float_as_uint(sy[(mrow + gid + 8) * 132 + k + tig + 4]);
                unsigned b0 = __float_as_uint(sxu[(n + gid) * 132 + k + tig]);
                unsigned b1 = __float_as_uint(sxu[(n + gid) * 132 + k + tig + 4]);
                mma_tf32(c0, c1, c2, c3, a0, a1, a2, a3, b0, b1);
            }
            float* d0 = g_score + ((size_t)b * TT + t0 + mrow + gid) * TT + u0 + n;
            float* d1 = d0 + (size_t)8 * TT;
            d0[2 * tig] = c0 * scl; d0[2 * tig + 1] = c1 * scl;
            d1[2 * tig] = c2 * scl; d1[2 * tig + 1] = c3 * scl;
        }
    }
}

// ---------------------------------------------------------------------------
// K3: flash softmax + P@V
// grid(8, 8, 32) = (t_tile, s, b), block(128) = 4 warps x 16 rows
// dyn smem = sw[64][68] + sv[64][136] + stats(3*64) = 52992 B
// ---------------------------------------------------------------------------
__global__ void __launch_bounds__(128) k_attn(const float* __restrict__ adj,
                                              float* __restrict__ out) {
    extern __shared__ float sm[];
    float* sw  = sm;                   // [64][68]  w / p tile
    float* sv  = sm + 64 * 68;         // [64][136] v chunk
    float* smx = sv + 64 * 136;        // running row max [64]
    float* sls = smx + 64;             // running row sum [64]
    float* sal = sls + 64;             // alpha [64]

    int tid = threadIdx.x, lane = tid & 31, w = tid >> 5;
    int gid = lane >> 2, tig = lane & 3;
    int t0 = blockIdx.x * 64, s = blockIdx.y, b = blockIdx.z;
    int mrow = w * 16;
    int rowe = mrow + (lane >> 1);     // elementwise row (2 lanes per row)
    int cole = (lane & 1) * 32;        // 32-col half per lane

    if (lane < 16) { smx[mrow + lane] = -1e30f; sls[mrow + lane] = 0.f; }

    float acc[16][4];
#pragma unroll
    for (int nt = 0; nt < 16; nt++) {
        acc[nt][0] = 0.f; acc[nt][1] = 0.f; acc[nt][2] = 0.f; acc[nt][3] = 0.f;
    }

    const float* scoreb = g_score + ((size_t)b * TT + t0) * TT;
    const float* adjb   = adj + (((size_t)b * SS + s) * TT + t0) * TT;
    const float* vb     = g_v + (size_t)b * TT * HSZ;

    for (int u0 = 0; u0 < TT; u0 += 64) {
        __syncthreads();  // sv from previous chunk fully consumed
        // cooperative load of v chunk [64 x 128] (coalesced float4)
        for (int f = tid; f < 64 * HSZ / 4; f += 128) {
            int r = f >> 5, c = (f & 31) * 4;
            *reinterpret_cast<float4*>(&sv[r * 136 + c]) =
                *reinterpret_cast<const float4*>(&vb[(size_t)(u0 + r) * HSZ + c]);
        }
        // pass 1: w = score * adj, stash raw in sw, track chunk max (warp-private rows)
        const float* srow = scoreb + (size_t)rowe * TT + u0 + cole;
        const float* arow = adjb + (size_t)rowe * TT + u0 + cole;
        float mx = -1e30f;
#pragma unroll
        for (int j = 0; j < 32; j += 4) {
            float4 sc = *reinterpret_cast<const float4*>(&srow[j]);
            float4 ad = *reinterpret_cast<const float4*>(&arow[j]);
            float t0v = sc.x * ad.x, t1v = sc.y * ad.y, t2v = sc.z * ad.z, t3v = sc.w * ad.w;
            sw[rowe * 68 + cole + j + 0] = t0v;
            sw[rowe * 68 + cole + j + 1] = t1v;
            sw[rowe * 68 + cole + j + 2] = t2v;
            sw[rowe * 68 + cole + j + 3] = t3v;
            mx = fmaxf(mx, fmaxf(fmaxf(t0v, t1v), fmaxf(t2v, t3v)));
        }
        mx = fmaxf(mx, __shfl_xor_sync(0xffffffffu, mx, 1));
        float mold = smx[rowe];
        float mnew = fmaxf(mold, mx);
        float alpha = __expf(mold - mnew);
        __syncwarp();
        // pass 2: p = exp(w - mnew), round to tf32, accumulate row sum
        float psum = 0.f;
#pragma unroll
        for (int j = 0; j < 32; j++) {
            float p = __expf(sw[rowe * 68 + cole + j] - mnew);
            psum += p;
            sw[rowe * 68 + cole + j] = f2tf_f(p);
        }
        psum += __shfl_xor_sync(0xffffffffu, psum, 1);
        if ((lane & 1) == 0) {
            smx[rowe] = mnew;
            sls[rowe] = sls[rowe] * alpha + psum;
            sal[rowe] = alpha;
        }
        __syncwarp();
        // rescale accumulators
        float al0 = sal[mrow + gid], al1 = sal[mrow + gid + 8];
#pragma unroll
        for (int nt = 0; nt < 16; nt++) {
            acc[nt][0] *= al0; acc[nt][1] *= al0;
            acc[nt][2] *= al1; acc[nt][3] *= al1;
        }
        __syncthreads();  // sv chunk ready (block-wide)
        // P @ V : [16 x 64] @ [64 x 128] per warp, tf32 mma
#pragma unroll
        for (int kk = 0; kk < 8; kk++) {
            int k = kk * 8;
            unsigned a0 = __float_as_uint(sw[(mrow + gid) * 68 + k + tig]);
            unsigned a1 = __float_as_uint(sw[(mrow + gid + 8) * 68 + k + tig]);
            unsigned a2 = __float_as_uint(sw[(mrow + gid) * 68 + k + tig + 4]);
            unsigned a3 = __float_as_uint(sw[(mrow + gid + 8) * 68 + k + tig + 4]);
#pragma unroll
            for (int nt = 0; nt < 16; nt++) {
                int n = nt * 8;
                unsigned b0 = __float_as_uint(sv[(k + tig) * 136 + n + gid]);
                unsigned b1 = __float_as_uint(sv[(k + tig + 4) * 136 + n + gid]);
                mma_tf32(acc[nt][0], acc[nt][1], acc[nt][2], acc[nt][3],
                         a0, a1, a2, a3, b0, b1);
            }
        }
    }
    __syncwarp();
    float li0 = 1.f / sls[mrow + gid];
    float li1 = 1.f / sls[mrow + gid + 8];
    float* ob = out + (((size_t)b * SS + s) * TT + t0 + mrow + gid) * HSZ;
#pragma unroll
    for (int nt = 0; nt < 16; nt++) {
        int n = nt * 8;
        float2 o0 = make_float2(acc[nt][0] * li0, acc[nt][1] * li0);
        float2 o1 = make_float2(acc[nt][2] * li1, acc[nt][3] * li1);
        *reinterpret_cast<float2*>(&ob[n + 2 * tig]) = o0;
        *reinterpret_cast<float2*>(&ob[(size_t)8 * HSZ + n + 2 * tig]) = o1;
    }
}

// ---------------------------------------------------------------------------
extern "C" void kernel_launch(void* const* d_in, const int* in_sizes, int n_in,
                              void* d_out, int out_size) {
    const float* x   = (const float*)d_in[0];
    const float* adj = (const float*)d_in[1];
    const float* Wq  = (const float*)d_in[2];
    const float* Wk  = (const float*)d_in[3];
    const float* Wv  = (const float*)d_in[4];
    float* out = (float*)d_out;

    const int smem_k1 = 128 * 132 * 4;            // 67584
    const int smem_k2a = 64 * 132 * 4;            // 33792
    const int smem_k2b = 2 * 64 * 132 * 4;        // 67584
    const int smem_k3 = (64 * 68 + 64 * 136 + 3 * 64) * 4;  // 52992

    cudaFuncSetAttribute(k_wqwk, cudaFuncAttributeMaxDynamicSharedMemorySize, smem_k1);
    cudaFuncSetAttribute(k_yv, cudaFuncAttributeMaxDynamicSharedMemorySize, smem_k2a);
    cudaFuncSetAttribute(k_score, cudaFuncAttributeMaxDynamicSharedMemorySize, smem_k2b);
    cudaFuncSetAttribute(k_attn, cudaFuncAttributeMaxDynamicSharedMemorySize, smem_k3);

    k_wqwk<<<128, 128, smem_k1>>>(Wq, Wk);
    k_yv<<<(BB * TT) / 64, 128, smem_k2a>>>(x, Wv);
    k_score<<<dim3(TT / 64, BB), 128, smem_k2b>>>(x);
    k_attn<<<dim3(TT / 64, SS, BB), 128, smem_k3>>>(adj, out);
}

// round 4
// speedup vs baseline: 1.3475x; 1.3475x over previous
#include <cuda_runtime.h>
#include <cstdint>
#include <cstddef>

// Problem constants
#define BB 32
#define SS 8
#define TT 512
#define CC 128
#define HSZ 128

// Scratch (device globals; no runtime allocation allowed)
__device__ float g_M[CC * CC];                       // Wq @ Wk^T, tf32-rounded
__device__ float g_y[BB * TT * CC];                  // x @ M, tf32-rounded
__device__ float g_v[BB * TT * HSZ];                 // x @ Wv, tf32, COLUMN-PERMUTED: h -> (h&7)*16 + (h>>3)
__device__ float g_score[(size_t)BB * TT * TT];      // fp32 scores (33.5 MB)

__device__ __forceinline__ unsigned f2tf(float x) {
    unsigned u;
    asm("cvt.rna.tf32.f32 %0, %1;" : "=r"(u) : "f"(x));
    return u;
}
__device__ __forceinline__ float f2tf_f(float x) { return __uint_as_float(f2tf(x)); }

__device__ __forceinline__ void mma_tf32(float& c0, float& c1, float& c2, float& c3,
                                         unsigned a0, unsigned a1, unsigned a2, unsigned a3,
                                         unsigned b0, unsigned b1) {
    asm volatile(
        "mma.sync.aligned.m16n8k8.row.col.f32.tf32.tf32.f32 "
        "{%0,%1,%2,%3},{%4,%5,%6,%7},{%8,%9},{%0,%1,%2,%3};\n"
        : "+f"(c0), "+f"(c1), "+f"(c2), "+f"(c3)
        : "r"(a0), "r"(a1), "r"(a2), "r"(a3), "r"(b0), "r"(b1));
}

// ---------------------------------------------------------------------------
// K1: M = Wq @ Wk^T  (fp32 FFMA, rounded to tf32 on store)
// ---------------------------------------------------------------------------
__global__ void k_wqwk(const float* __restrict__ Wq, const float* __restrict__ Wk) {
    extern __shared__ float sm[];  // sWk[128][132]
    int tid = threadIdx.x;
    int c1 = blockIdx.x;
    for (int i = tid; i < CC * CC; i += 128) {
        sm[(i >> 7) * 132 + (i & 127)] = Wk[i];
    }
    __syncthreads();
    const float* wqr = Wq + c1 * CC;
    float acc = 0.f;
#pragma unroll 8
    for (int h = 0; h < CC; h++) acc += wqr[h] * sm[tid * 132 + h];
    g_M[c1 * CC + tid] = f2tf_f(acc);
}

// ---------------------------------------------------------------------------
// K2a: y = x @ M,  v = x @ Wv   (tf32 mma). v stored column-permuted.
// grid(B*T/64), block(128), dyn smem = 64*132*4
// ---------------------------------------------------------------------------
__global__ void __launch_bounds__(128) k_yv(const float* __restrict__ x,
                                            const float* __restrict__ Wv) {
    extern __shared__ float sm[];  // sx[64][132] tf32-rounded
    int tid = threadIdx.x;
    int row0 = blockIdx.x * 64;
    for (int f = tid; f < 64 * CC / 4; f += 128) {
        int r = f >> 5, c = (f & 31) * 4;
        float4 v4 = *reinterpret_cast<const float4*>(&x[(size_t)(row0 + r) * CC + c]);
        float4 o;
        o.x = f2tf_f(v4.x); o.y = f2tf_f(v4.y); o.z = f2tf_f(v4.z); o.w = f2tf_f(v4.w);
        *reinterpret_cast<float4*>(&sm[r * 132 + c]) = o;
    }
    __syncthreads();
    int lane = tid & 31, w = tid >> 5;
    int gid = lane >> 2, tig = lane & 3;
    int mrow = w * 16;
    for (int nt = 0; nt < 32; nt++) {
        bool isv = nt >= 16;
        const float* Bsrc = isv ? Wv : g_M;
        int nt8 = nt & 15;
        int n = nt8 * 8;
        float c0 = 0, c1 = 0, c2 = 0, c3 = 0;
#pragma unroll
        for (int kk = 0; kk < 16; kk++) {
            int k = kk * 8;
            unsigned a0 = __float_as_uint(sm[(mrow + gid) * 132 + k + tig]);
            unsigned a1 = __float_as_uint(sm[(mrow + gid + 8) * 132 + k + tig]);
            unsigned a2 = __float_as_uint(sm[(mrow + gid) * 132 + k + tig + 4]);
            unsigned a3 = __float_as_uint(sm[(mrow + gid + 8) * 132 + k + tig + 4]);
            float bv0 = Bsrc[(k + tig) * CC + n + gid];
            float bv1 = Bsrc[(k + tig + 4) * CC + n + gid];
            unsigned b0 = isv ? f2tf(bv0) : __float_as_uint(bv0);
            unsigned b1 = isv ? f2tf(bv1) : __float_as_uint(bv1);
            mma_tf32(c0, c1, c2, c3, a0, a1, a2, a3, b0, b1);
        }
        int r0 = row0 + mrow + gid;
        if (!isv) {
            g_y[(size_t)r0 * CC + n + 2 * tig]           = f2tf_f(c0);
            g_y[(size_t)r0 * CC + n + 2 * tig + 1]       = f2tf_f(c1);
            g_y[(size_t)(r0 + 8) * CC + n + 2 * tig]     = f2tf_f(c2);
            g_y[(size_t)(r0 + 8) * CC + n + 2 * tig + 1] = f2tf_f(c3);
        } else {
            // permuted store: col h -> (h&7)*16 + (h>>3)
            int col0 = 32 * tig + nt8;
            g_v[(size_t)r0 * HSZ + col0]            = f2tf_f(c0);
            g_v[(size_t)r0 * HSZ + col0 + 16]       = f2tf_f(c1);
            g_v[(size_t)(r0 + 8) * HSZ + col0]      = f2tf_f(c2);
            g_v[(size_t)(r0 + 8) * HSZ + col0 + 16] = f2tf_f(c3);
        }
    }
}

// ---------------------------------------------------------------------------
// K2b: score[b,t,u] = (y[b,t,:] . x[b,u,:]) * C^-0.5
// A-fragments (y) register-resident; B (x chunk) in smem, permuted so each
// thread's 32 B values (b0/b1 over all kk) are contiguous: col c -> (c&3)*36 + (c>>2)
// grid(8, 32), block(128), dyn smem = 64*144*4 = 36864
// ---------------------------------------------------------------------------
__global__ void __launch_bounds__(128) k_score(const float* __restrict__ x) {
    extern __shared__ float sxp[];  // [64][144] permuted tf32 x chunk
    int tid = threadIdx.x;
    int lane = tid & 31, w = tid >> 5, g = lane >> 2, t = lane & 3;
    int b = blockIdx.y;
    int t0 = blockIdx.x * 64;
    int mrow = w * 16;
    int R0 = t0 + mrow + g, R1 = R0 + 8;
    const float scl = 0.08838834764831843f;  // 128^-0.5

    // A fragments from g_y (already tf32)
    unsigned a0r[16], a1r[16], a2r[16], a3r[16];
    const float* y0 = g_y + (size_t)(b * TT + R0) * CC;
    const float* y1 = g_y + (size_t)(b * TT + R1) * CC;
#pragma unroll
    for (int kk = 0; kk < 16; kk++) {
        int c = 8 * kk + t;
        a0r[kk] = __float_as_uint(y0[c]);
        a1r[kk] = __float_as_uint(y1[c]);
        a2r[kk] = __float_as_uint(y0[c + 4]);
        a3r[kk] = __float_as_uint(y1[c + 4]);
    }

    for (int u0 = 0; u0 < TT; u0 += 64) {
        __syncthreads();
        // cooperative permuted load of x chunk
        for (int f = tid; f < 64 * CC / 4; f += 128) {
            int r = f >> 5, c4 = f & 31;
            float4 v4 = *reinterpret_cast<const float4*>(&x[(size_t)(b * TT + u0 + r) * CC + c4 * 4]);
            float* dst = &sxp[r * 144 + c4];  // element j goes to j*36 + c4
            dst[0]   = f2tf_f(v4.x);
            dst[36]  = f2tf_f(v4.y);
            dst[72]  = f2tf_f(v4.z);
            dst[108] = f2tf_f(v4.w);
        }
        __syncthreads();
#pragma unroll
        for (int nt = 0; nt < 8; nt++) {
            int brow = nt * 8 + g;
            // FIXED: full K=128 coverage -> 32 floats (8 x LDS.128), was 16 (OOB reads)
            float bf[32];
            const float4* bp = reinterpret_cast<const float4*>(&sxp[brow * 144 + t * 36]);
#pragma unroll
            for (int j = 0; j < 8; j++) *reinterpret_cast<float4*>(&bf[4 * j]) = bp[j];
            float c0 = 0, c1 = 0, c2 = 0, c3 = 0;
#pragma unroll
            for (int kk = 0; kk < 16; kk++) {
                mma_tf32(c0, c1, c2, c3, a0r[kk], a1r[kk], a2r[kk], a3r[kk],
                         __float_as_uint(bf[2 * kk]), __float_as_uint(bf[2 * kk + 1]));
            }
            float* d0 = g_score + ((size_t)b * TT + R0) * TT + u0 + nt * 8;
            float* d1 = g_score + ((size_t)b * TT + R1) * TT + u0 + nt * 8;
            *reinterpret_cast<float2*>(&d0[2 * t]) = make_float2(c0 * scl, c1 * scl);
            *reinterpret_cast<float2*>(&d1[2 * t]) = make_float2(c2 * scl, c3 * scl);
        }
    }
}

// ---------------------------------------------------------------------------
// K3: flash softmax + P@V
// score & adj gathered directly into mma A-fragment registers (no smem tile);
// softmax state (m, l) register-resident per quad; V from permuted smem via LDS.128.
// grid(8, 8, 32) = (t_tile, s, b), block(128) = 4 warps x 16 rows
// dyn smem = 64*132*4 = 33792
// ---------------------------------------------------------------------------
__global__ void __launch_bounds__(128) k_attn(const float* __restrict__ adj,
                                              float* __restrict__ out) {
    extern __shared__ float svp[];  // [64][132] permuted V chunk (tf32)

    int tid = threadIdx.x, lane = tid & 31, w = tid >> 5;
    int g = lane >> 2, t = lane & 3;
    int t0 = blockIdx.x * 64, s = blockIdx.y, b = blockIdx.z;
    int mrow = w * 16;
    int R0 = t0 + mrow + g, R1 = R0 + 8;

    const float* srow0 = g_score + ((size_t)b * TT + R0) * TT;
    const float* srow1 = g_score + ((size_t)b * TT + R1) * TT;
    const float* arow0 = adj + (((size_t)b * SS + s) * TT + R0) * TT;
    const float* arow1 = adj + (((size_t)b * SS + s) * TT + R1) * TT;
    const float4* vb4 = reinterpret_cast<const float4*>(g_v + (size_t)b * TT * HSZ);
    float4* svp4 = reinterpret_cast<float4*>(svp);

    float m0 = -1e30f, m1 = -1e30f, l0 = 0.f, l1 = 0.f;
    float acc[16][4];
#pragma unroll
    for (int nt = 0; nt < 16; nt++) {
        acc[nt][0] = 0.f; acc[nt][1] = 0.f; acc[nt][2] = 0.f; acc[nt][3] = 0.f;
    }

    for (int u0 = 0; u0 < TT; u0 += 64) {
        __syncthreads();  // previous chunk's svp reads complete
        // straight copy of permuted V chunk (rows contiguous), conflict-free
        {
            const float4* src = vb4 + (size_t)u0 * (HSZ / 4);
#pragma unroll
            for (int it = 0; it < 16; it++) {
                int f = tid + it * 128;
                int r = f >> 5, c4 = f & 31;
                svp4[r * 33 + c4] = src[r * 32 + c4];
            }
        }
        // gather w = score*adj directly in fragment layout
        float w0[8], w1[8], w2[8], w3[8];
#pragma unroll
        for (int kk = 0; kk < 8; kk++) {
            int c = u0 + 8 * kk + t;
            w0[kk] = srow0[c] * arow0[c];
            w1[kk] = srow1[c] * arow1[c];
            w2[kk] = srow0[c + 4] * arow0[c + 4];
            w3[kk] = srow1[c + 4] * arow1[c + 4];
        }
        // chunk row max (quad reduce)
        float mx0 = -1e30f, mx1 = -1e30f;
#pragma unroll
        for (int kk = 0; kk < 8; kk++) {
            mx0 = fmaxf(mx0, fmaxf(w0[kk], w2[kk]));
            mx1 = fmaxf(mx1, fmaxf(w1[kk], w3[kk]));
        }
        mx0 = fmaxf(mx0, __shfl_xor_sync(0xffffffffu, mx0, 1));
        mx0 = fmaxf(mx0, __shfl_xor_sync(0xffffffffu, mx0, 2));
        mx1 = fmaxf(mx1, __shfl_xor_sync(0xffffffffu, mx1, 1));
        mx1 = fmaxf(mx1, __shfl_xor_sync(0xffffffffu, mx1, 2));
        float m0n = fmaxf(m0, mx0), m1n = fmaxf(m1, mx1);
        float al0 = __expf(m0 - m0n), al1 = __expf(m1 - m1n);
        m0 = m0n; m1 = m1n;
        // exp + row sums
        float ps0 = 0.f, ps1 = 0.f;
#pragma unroll
        for (int kk = 0; kk < 8; kk++) {
            w0[kk] = __expf(w0[kk] - m0n); ps0 += w0[kk];
            w2[kk] = __expf(w2[kk] - m0n); ps0 += w2[kk];
            w1[kk] = __expf(w1[kk] - m1n); ps1 += w1[kk];
            w3[kk] = __expf(w3[kk] - m1n); ps1 += w3[kk];
        }
        ps0 += __shfl_xor_sync(0xffffffffu, ps0, 1);
        ps0 += __shfl_xor_sync(0xffffffffu, ps0, 2);
        ps1 += __shfl_xor_sync(0xffffffffu, ps1, 1);
        ps1 += __shfl_xor_sync(0xffffffffu, ps1, 2);
        l0 = l0 * al0 + ps0;
        l1 = l1 * al1 + ps1;
        // rescale accumulators
#pragma unroll
        for (int nt = 0; nt < 16; nt++) {
            acc[nt][0] *= al0; acc[nt][1] *= al0;
            acc[nt][2] *= al1; acc[nt][3] *= al1;
        }
        __syncthreads();  // svp chunk ready
        // P @ V : per kk, B fragments = 8 LDS.128 covering all 16 n-tiles
#pragma unroll
        for (int kk = 0; kk < 8; kk++) {
            unsigned a0 = f2tf(w0[kk]);
            unsigned a1 = f2tf(w1[kk]);
            unsigned a2 = f2tf(w2[kk]);
            unsigned a3 = f2tf(w3[kk]);
            int row_lo = 8 * kk + t, row_hi = row_lo + 4;
            float bl[16], bh[16];
            const float4* pl = &svp4[row_lo * 33 + g * 4];
            const float4* ph = &svp4[row_hi * 33 + g * 4];
#pragma unroll
            for (int j = 0; j < 4; j++) {
                *reinterpret_cast<float4*>(&bl[4 * j]) = pl[j];
                *reinterpret_cast<float4*>(&bh[4 * j]) = ph[j];
            }
#pragma unroll
            for (int nt = 0; nt < 16; nt++) {
                mma_tf32(acc[nt][0], acc[nt][1], acc[nt][2], acc[nt][3],
                         a0, a1, a2, a3,
                         __float_as_uint(bl[nt]), __float_as_uint(bh[nt]));
            }
        }
    }
    // epilogue
    float rl0 = 1.f / l0, rl1 = 1.f / l1;
    float* ob0 = out + (((size_t)b * SS + s) * TT + R0) * HSZ;
    float* ob1 = out + (((size_t)b * SS + s) * TT + R1) * HSZ;
#pragma unroll
    for (int nt = 0; nt < 16; nt++) {
        int c = 8 * nt + 2 * t;
        *reinterpret_cast<float2*>(&ob0[c]) = make_float2(acc[nt][0] * rl0, acc[nt][1] * rl0);
        *reinterpret_cast<float2*>(&ob1[c]) = make_float2(acc[nt][2] * rl1, acc[nt][3] * rl1);
    }
}

// ---------------------------------------------------------------------------
extern "C" void kernel_launch(void* const* d_in, const int* in_sizes, int n_in,
                              void* d_out, int out_size) {
    const float* x   = (const float*)d_in[0];
    const float* adj = (const float*)d_in[1];
    const float* Wq  = (const float*)d_in[2];
    const float* Wk  = (const float*)d_in[3];
    const float* Wv  = (const float*)d_in[4];
    float* out = (float*)d_out;

    const int smem_k1 = 128 * 132 * 4;     // 67584
    const int smem_k2a = 64 * 132 * 4;     // 33792
    const int smem_k2b = 64 * 144 * 4;     // 36864
    const int smem_k3 = 64 * 132 * 4;      // 33792

    cudaFuncSetAttribute(k_wqwk, cudaFuncAttributeMaxDynamicSharedMemorySize, smem_k1);
    cudaFuncSetAttribute(k_yv, cudaFuncAttributeMaxDynamicSharedMemorySize, smem_k2a);
    cudaFuncSetAttribute(k_score, cudaFuncAttributeMaxDynamicSharedMemorySize, smem_k2b);
    cudaFuncSetAttribute(k_attn, cudaFuncAttributeMaxDynamicSharedMemorySize, smem_k3);

    k_wqwk<<<128, 128, smem_k1>>>(Wq, Wk);
    k_yv<<<(BB * TT) / 64, 128, smem_k2a>>>(x, Wv);
    k_score<<<dim3(TT / 64, BB), 128, smem_k2b>>>(x);
    k_attn<<<dim3(TT / 64, SS, BB), 128, smem_k3>>>(adj, out);
}